// round 15
// baseline (speedup 1.0000x reference)
#include <cuda_runtime.h>
#include <cuda_fp16.h>
#include <cooperative_groups.h>
#include <math.h>
#include <stdint.h>

namespace cg = cooperative_groups;

// Problem constants
#define B_    32
#define C_    1536
#define HW_   1024      // 32*32
#define HID_  512
#define LDIM_ 128
#define MCL_  64
#define GDIM_ 256
#define OUTD_ (GDIM_ + LDIM_*MCL_)   // 8448
#define EPSV  1e-12f

// -------------------------------------------------------------------------
// Scratch (__device__ globals: allocation-free, graph-capture safe)
// -------------------------------------------------------------------------
__device__ __align__(256) __half g_x16[(size_t)B_ * C_ * HW_];    // channel-major fp16
__device__ __align__(256) __half g_W1[1024 * C_];
__device__ __align__(256) __half g_W2[256 * HID_];                // 0..127 cf, 128..191 sc
__device__ __align__(256) float  g_b1s[1024];
__device__ __align__(256) float  g_b2s[256];
__device__ __align__(256) __half g_Ht[(size_t)B_ * 1024 * HW_];   // channel-major fp16
__device__ __align__(256) float  g_F[(size_t)B_ * LDIM_ * HW_];
__device__ __align__(256) float  g_P[(size_t)B_ * MCL_  * HW_];
__device__ __align__(256) float  g_aggp[4 * B_ * LDIM_ * MCL_];   // 4 HW-slices

// -------------------------------------------------------------------------
// PTX helpers
// -------------------------------------------------------------------------
__device__ __forceinline__ uint32_t smem_u32(const void* p) {
    uint32_t a;
    asm("{ .reg .u64 t; cvta.to.shared.u64 t, %1; cvt.u32.u64 %0, t; }" : "=r"(a) : "l"(p));
    return a;
}
__device__ __forceinline__ void cp16(uint32_t dst, const void* src) {
    asm volatile("cp.async.cg.shared.global [%0], [%1], 16;" :: "r"(dst), "l"(src));
}
#define CP_COMMIT() asm volatile("cp.async.commit_group;" ::: "memory")
#define CP_WAIT(n)  asm volatile("cp.async.wait_group %0;" :: "n"(n) : "memory")

__device__ __forceinline__ void ldsm4(uint32_t* r, uint32_t addr) {
    asm volatile("ldmatrix.sync.aligned.m8n8.x4.shared.b16 {%0,%1,%2,%3}, [%4];"
        : "=r"(r[0]), "=r"(r[1]), "=r"(r[2]), "=r"(r[3]) : "r"(addr));
}
__device__ __forceinline__ void ldsm4t(uint32_t* r, uint32_t addr) {
    asm volatile("ldmatrix.sync.aligned.m8n8.x4.trans.shared.b16 {%0,%1,%2,%3}, [%4];"
        : "=r"(r[0]), "=r"(r[1]), "=r"(r[2]), "=r"(r[3]) : "r"(addr));
}
__device__ __forceinline__ void mma16816(float* c, const uint32_t* a, const uint32_t* b) {
    asm volatile(
        "mma.sync.aligned.m16n8k16.row.col.f32.f16.f16.f32 "
        "{%0,%1,%2,%3}, {%4,%5,%6,%7}, {%8,%9}, {%0,%1,%2,%3};"
        : "+f"(c[0]), "+f"(c[1]), "+f"(c[2]), "+f"(c[3])
        : "r"(a[0]), "r"(a[1]), "r"(a[2]), "r"(a[3]), "r"(b[0]), "r"(b[1]));
}
__device__ __forceinline__ uint32_t swz(uint32_t off) {       // 128B-row swizzle (A tiles)
    return off ^ ((off >> 3) & 0x70);
}
__device__ __forceinline__ uint32_t swzB(uint32_t off) {      // 256B-row swizzle (B tiles)
    return off ^ ((off >> 4) & 0x70);
}

// -------------------------------------------------------------------------
// prep_all: weight stacking/fp16 + token MLP + x fp32->fp16 convert.
// blocks [0,1024): W1 rows; [1024,1280): W2 rows; [1280,1312): token batches;
// [1312,2080): x convert (each block 16384 float4s).
// -------------------------------------------------------------------------
__global__ void __launch_bounds__(256)
prep_all(const float* __restrict__ cf_w1, const float* __restrict__ cf_b1,
         const float* __restrict__ sc_w1, const float* __restrict__ sc_b1,
         const float* __restrict__ cf_w2, const float* __restrict__ cf_b2,
         const float* __restrict__ sc_w2, const float* __restrict__ sc_b2,
         const float* __restrict__ x,
         const float* __restrict__ t,
         const float* __restrict__ tw1, const float* __restrict__ tb1,
         const float* __restrict__ tw2, const float* __restrict__ tb2,
         float* __restrict__ out)
{
    const int bx = blockIdx.x;
    const int tid = threadIdx.x;

    if (bx < 1024) {                          // --- W1 row ---
        const int r = bx;
        const float* src = (r < HID_) ? cf_w1 + (size_t)r * C_ : sc_w1 + (size_t)(r - HID_) * C_;
        for (int i = tid; i < C_; i += 256)
            g_W1[(size_t)r * C_ + i] = __float2half_rn(src[i]);
        if (tid == 0)
            g_b1s[r] = (r < HID_) ? cf_b1[r] : sc_b1[r - HID_];
        return;
    }
    if (bx < 1280) {                          // --- W2 row ---
        const int r = bx - 1024;
        const float* src = (r < LDIM_) ? cf_w2 + (size_t)r * HID_
                         : (r < LDIM_ + MCL_) ? sc_w2 + (size_t)(r - LDIM_) * HID_ : nullptr;
        for (int i = tid; i < HID_; i += 256)
            g_W2[(size_t)r * HID_ + i] = __float2half_rn(src ? src[i] : 0.f);
        if (tid == 0)
            g_b2s[r] = (r < LDIM_) ? cf_b2[r] : (r < LDIM_ + MCL_) ? sc_b2[r - LDIM_] : 0.f;
        return;
    }
    if (bx >= 1312) {                         // --- x convert (natural layout) ---
        const size_t cid = bx - 1312;
        #pragma unroll 4
        for (int q = 0; q < 64; q++) {
            size_t fidx = cid * 16384 + (size_t)q * 256 + tid;
            float4 v = *(const float4*)(x + fidx * 4);
            __half h4[4];
            h4[0] = __float2half_rn(v.x); h4[1] = __float2half_rn(v.y);
            h4[2] = __float2half_rn(v.z); h4[3] = __float2half_rn(v.w);
            *(uint2*)(g_x16 + fidx * 4) = *(const uint2*)h4;
        }
        return;
    }

    // --- token MLP for batch b ---
    const int b = bx - 1280;
    const int warp = tid >> 5, lane = tid & 31;

    __shared__ float ts[C_];
    __shared__ float h[HID_];
    __shared__ float tk[GDIM_];
    __shared__ float red[8];

    for (int i = tid; i < C_; i += 256) ts[i] = t[(size_t)b * C_ + i];
    __syncthreads();

    for (int j = warp; j < HID_; j += 8) {
        const float* wr = tw1 + (size_t)j * C_;
        float s = 0.f;
        for (int k = lane * 4; k < C_; k += 128) {
            float4 w4 = *(const float4*)(wr + k);
            float4 t4 = *(const float4*)(ts + k);
            s += w4.x*t4.x + w4.y*t4.y + w4.z*t4.z + w4.w*t4.w;
        }
        #pragma unroll
        for (int o = 16; o; o >>= 1) s += __shfl_xor_sync(0xffffffffu, s, o);
        if (lane == 0) h[j] = fmaxf(s + tb1[j], 0.f);
    }
    __syncthreads();

    for (int j = warp; j < GDIM_; j += 8) {
        const float* wr = tw2 + (size_t)j * HID_;
        float s = 0.f;
        for (int k = lane * 4; k < HID_; k += 128) {
            float4 w4 = *(const float4*)(wr + k);
            float4 h4 = *(const float4*)(h + k);
            s += w4.x*h4.x + w4.y*h4.y + w4.z*h4.z + w4.w*h4.w;
        }
        #pragma unroll
        for (int o = 16; o; o >>= 1) s += __shfl_xor_sync(0xffffffffu, s, o);
        if (lane == 0) tk[j] = s + tb2[j];
    }
    __syncthreads();

    float v = tk[tid];
    float sq = v * v;
    #pragma unroll
    for (int o = 16; o; o >>= 1) sq += __shfl_xor_sync(0xffffffffu, sq, o);
    if (lane == 0) red[warp] = sq;
    __syncthreads();
    if (warp == 0) {
        float r = (lane < 8) ? red[lane] : 0.f;
        #pragma unroll
        for (int o = 4; o; o >>= 1) r += __shfl_xor_sync(0xffffffffu, r, o);
        if (lane == 0) red[0] = r;
    }
    __syncthreads();
    const float inv = 1.f / fmaxf(sqrtf(red[0]), EPSV);
    out[(size_t)b * OUTD_ + tid] = v * inv;
}

// -------------------------------------------------------------------------
// Tensor-core GEMM via mma.sync (single-pass fp16, fp32 accum).
// A: weights, K-major rows (swz128). B: activations in NATURAL channel-major
// layout [CH][HW] — tiles staged as [64 k][256B n] (swzB) and loaded with
// ldmatrix.trans (no global transpose anywhere).
// CTA = CTAM x 128, 8 warps @ (CTAM/2)x32, BK=64, 3-stage cp.async pipeline,
// __launch_bounds__(256,2).
// EPI=1: bias+relu -> fp16 -> CHANNEL-major Ht (direct rows, no transpose).
// EPI=2: bias -> fp32, contiguous M rows to OutF, channel-major.
// KOFF: channel offset into B (Ht half for P).
// -------------------------------------------------------------------------
template<int KDIM, int CH, int EPI, int CTAM, int KOFF>
__global__ void __launch_bounds__(256, 2)
gemm_mma(const __half* __restrict__ Ag, const __half* __restrict__ Bg,
         const float* __restrict__ bias,
         __half* __restrict__ OutH, float* __restrict__ OutF)
{
    constexpr int NCHUNK  = KDIM / 64;
    constexpr int A_BYTES = CTAM * 128;
    constexpr int STAGE   = A_BYTES + 16384;        // B tile: 64 x 256B
    constexpr int MB = CTAM / 32, NB = 4, NBP = 2;  // warp tile (CTAM/2) x 32
    constexpr int AIT = (CTAM * 8) / 256;

    extern __shared__ __align__(1024) char smem[];
    const uint32_t sbase = smem_u32(smem);
    float* bias_s = (float*)smem;

    const int tid  = threadIdx.x;
    const int wid  = tid >> 5, lane = tid & 31;
    const int n0   = blockIdx.x * 128;
    const int m0   = blockIdx.y * CTAM;
    const int bz   = blockIdx.z;

    const int warp_m = (wid >> 2) * (CTAM / 2);
    const int warp_n = (wid & 3) * 32;

    if (tid < CTAM) bias_s[tid] = bias[m0 + tid];

    const size_t bChanBase = (size_t)bz * CH + KOFF;

    auto load_stage = [&](int c, int stage) {
        const uint32_t base = sbase + 1024 + stage * STAGE;
        #pragma unroll
        for (int q = 0; q < AIT; q++) {
            int idx = tid + q * 256;
            int row = idx >> 3, seg = idx & 7;
            cp16(base + swz(row * 128 + seg * 16),
                 Ag + (size_t)(m0 + row) * KDIM + c * 64 + seg * 8);
        }
        const uint32_t bbuf = base + A_BYTES;
        #pragma unroll
        for (int q = 0; q < 4; q++) {
            int idx = tid + q * 256;                // 1024 chunks: 64 rows x 16
            int row = idx >> 4, seg = idx & 15;
            cp16(bbuf + swzB(row * 256 + seg * 16),
                 Bg + (bChanBase + c * 64 + row) * HW_ + n0 + seg * 8);
        }
        CP_COMMIT();
    };

    float acc[MB][NB][4];
    #pragma unroll
    for (int i = 0; i < MB; i++)
        #pragma unroll
        for (int j = 0; j < NB; j++)
            #pragma unroll
            for (int r = 0; r < 4; r++) acc[i][j][r] = 0.f;

    load_stage(0, 0);
    if (NCHUNK > 1) load_stage(1, 1);

    #pragma unroll 1
    for (int c = 0; c < NCHUNK; c++) {
        if (c + 1 < NCHUNK) { CP_WAIT(1); }
        else                { CP_WAIT(0); }
        __syncthreads();

        if (c + 2 < NCHUNK) load_stage(c + 2, (c + 2) % 3);

        const uint32_t aBase = sbase + 1024 + (c % 3) * STAGE;
        const uint32_t bBase = aBase + A_BYTES;
        const int grp = lane >> 3;

        #pragma unroll
        for (int s = 0; s < 4; s++) {
            uint32_t af[MB][4], bf[NB][2];
            #pragma unroll
            for (int mb = 0; mb < MB; mb++) {
                int row = warp_m + mb * 16 + (lane & 15);
                uint32_t off = swz(row * 128 + s * 32 + ((lane >> 4) << 4));
                ldsm4(af[mb], aBase + off);
            }
            // B via trans ldmatrix from [k][n] tile:
            // mats: (k0-7,n0-7) (k8-15,n0-7) (k0-7,n8-15) (k8-15,n8-15)
            #pragma unroll
            for (int nbp = 0; nbp < NBP; nbp++) {
                int krow = s * 16 + ((grp & 1) << 3) + (lane & 7);
                int ncol = warp_n + nbp * 16 + ((grp >> 1) << 3);
                uint32_t off = swzB(krow * 256 + ncol * 2);
                uint32_t t[4];
                ldsm4t(t, bBase + off);
                bf[nbp*2][0]   = t[0]; bf[nbp*2][1]   = t[1];
                bf[nbp*2+1][0] = t[2]; bf[nbp*2+1][1] = t[3];
            }
            #pragma unroll
            for (int mb = 0; mb < MB; mb++)
                #pragma unroll
                for (int nb = 0; nb < NB; nb++) mma16816(acc[mb][nb], af[mb], bf[nb]);
        }
    }
    __syncthreads();

    const int qr = lane >> 2, qc = (lane & 3) * 2;

    if (EPI == 1) {
        // stage channel-major: sC[m][n], pitch 132 (no transpose needed)
        constexpr int PITCH = 132;
        float* sC = (float*)(smem + 1024);
        #pragma unroll
        for (int mb = 0; mb < MB; mb++)
            #pragma unroll
            for (int nb = 0; nb < NB; nb++)
                #pragma unroll
                for (int r = 0; r < 4; r++) {
                    int m = warp_m + mb * 16 + qr + ((r >> 1) << 3);
                    int n = warp_n + nb * 8 + qc + (r & 1);
                    sC[m * PITCH + n] = fmaxf(acc[mb][nb][r] + bias_s[m], 0.f);
                }
        __syncthreads();
        #pragma unroll
        for (int q = 0; q < 8; q++) {
            int idx = tid + q * 256;                // 2048 = 128 m x 16 segs
            int m = idx >> 4, sg = idx & 15;
            const float* src = sC + m * PITCH + sg * 8;
            __half h8[8];
            #pragma unroll
            for (int j = 0; j < 8; j++) h8[j] = __float2half_rn(src[j]);
            size_t g = ((size_t)bz * 1024 + m0 + m) * HW_ + n0 + sg * 8;
            *(uint4*)(OutH + g) = *(const uint4*)h8;
        }
    } else {
        #pragma unroll
        for (int mb = 0; mb < MB; mb++)
            #pragma unroll
            for (int nb = 0; nb < NB; nb++)
                #pragma unroll
                for (int r = 0; r < 4; r++) {
                    int ml = warp_m + mb * 16 + qr + ((r >> 1) << 3);
                    int n  = warp_n + nb * 8 + qc + (r & 1);
                    OutF[((size_t)bz * CTAM + m0 + ml) * HW_ + n0 + n]
                        = acc[mb][nb][r] + bias_s[ml];
                }
    }
}

#define SMEM_G(CTAM) (1024 + 3 * ((CTAM) * 128 + 16384))

// -------------------------------------------------------------------------
// Cluster Sinkhorn (R11 winner, unchanged)
// -------------------------------------------------------------------------
#define SK_COLS 512
#define SK_SMEM ((64 * SK_COLS + 72 + SK_COLS + 2 * 66 + 2 * 66) * 4)

__global__ void __launch_bounds__(1024) __cluster_dims__(2, 1, 1)
sinkhorn_cluster(float* __restrict__ Pg, const float* __restrict__ dust)
{
    extern __shared__ float sk[];
    float* Zs = sk;
    float* u  = sk + 64 * SK_COLS;
    float* v  = u + 72;
    float* pm = v + SK_COLS;
    float* ps = pm + 2 * 66;

    cg::cluster_group cluster = cg::this_cluster();
    const int rank = blockIdx.x & 1;
    const int b    = blockIdx.x >> 1;
    float* Z = Pg + (size_t)b * MCL_ * HW_ + rank * SK_COLS;
    const int tid = threadIdx.x, warp = tid >> 5, lane = tid & 31;

    const float alpha = dust[0];
    const float norm_c     = -logf((float)(MCL_ + HW_));
    const float log_mu     = norm_c;
    const float log_mu_bin = logf((float)(HW_ - MCL_)) + norm_c;
    const float log_nu     = norm_c;

    for (int idx = tid; idx < 64 * SK_COLS; idx += 1024)
        Zs[idx] = Z[(size_t)(idx >> 9) * HW_ + (idx & 511)];
    if (tid < SK_COLS) v[tid] = 0.f;
    __syncthreads();

    float* peer_pm = cluster.map_shared_rank(pm, rank ^ 1);
    float* peer_ps = cluster.map_shared_rank(ps, rank ^ 1);

    for (int it = 0; it < 3; it++) {
        float* pmx = pm + (it & 1) * 66;
        float* psm = ps + (it & 1) * 66;
        float* qmx = peer_pm + (it & 1) * 66;
        float* qsm = peer_ps + (it & 1) * 66;

        for (int i = warp; i < MCL_; i += 32) {
            const float* zr = Zs + i * SK_COLS;
            float mx = -3.0e38f, s = 0.f;
            for (int j = lane; j < SK_COLS; j += 32) {
                float zv = zr[j] + v[j];
                if (zv > mx) { s = s * __expf(mx - zv) + 1.f; mx = zv; }
                else           s += __expf(zv - mx);
            }
            #pragma unroll
            for (int o = 16; o; o >>= 1) {
                float mo = __shfl_xor_sync(0xffffffffu, mx, o);
                float so = __shfl_xor_sync(0xffffffffu, s,  o);
                float m2 = fmaxf(mx, mo);
                s  = s * __expf(mx - m2) + so * __expf(mo - m2);
                mx = m2;
            }
            if (lane == 0) { pmx[i] = mx; psm[i] = s; }
        }
        if (warp == 0) {
            float mx = -3.0e38f, s = 0.f;
            for (int j = lane; j < SK_COLS; j += 32) {
                float zv = v[j];
                if (zv > mx) { s = s * __expf(mx - zv) + 1.f; mx = zv; }
                else           s += __expf(zv - mx);
            }
            #pragma unroll
            for (int o = 16; o; o >>= 1) {
                float mo = __shfl_xor_sync(0xffffffffu, mx, o);
                float so = __shfl_xor_sync(0xffffffffu, s,  o);
                float m2 = fmaxf(mx, mo);
                s  = s * __expf(mx - m2) + so * __expf(mo - m2);
                mx = m2;
            }
            if (lane == 0) { pmx[MCL_] = mx; psm[MCL_] = s; }
        }
        cluster.sync();

        if (tid <= MCL_) {
            float mA = pmx[tid], sA = psm[tid];
            float mB = qmx[tid], sB = qsm[tid];
            float M = fmaxf(mA, mB);
            float lse = M + __logf(sA * __expf(mA - M) + sB * __expf(mB - M));
            u[tid] = (tid < MCL_) ? (log_mu - lse) : (log_mu_bin - (alpha + lse));
        }
        __syncthreads();

        if (tid < SK_COLS) {
            const int j = tid;
            float mx = alpha + u[MCL_];
            float s  = 1.f;
            #pragma unroll 4
            for (int i = 0; i < MCL_; i++) {
                float zv = Zs[i * SK_COLS + j] + u[i];
                if (zv > mx) { s = s * __expf(mx - zv) + 1.f; mx = zv; }
                else           s += __expf(zv - mx);
            }
            v[j] = log_nu - (mx + __logf(s));
        }
        __syncthreads();
    }

    for (int idx = tid; idx < 64 * SK_COLS; idx += 1024) {
        int i = idx >> 9, j = idx & 511;
        Z[(size_t)i * HW_ + j] = __expf(Zs[idx] + u[i] + v[j] - norm_c);
    }
    cluster.sync();
}

// -------------------------------------------------------------------------
// VLAD aggregation, stage 1: partial agg over an HW quarter.
// -------------------------------------------------------------------------
__global__ void __launch_bounds__(256)
agg_partial(const float* __restrict__ Fg, const float* __restrict__ Pg)
{
    const int sl = blockIdx.x;
    const int b  = blockIdx.y;
    const float* f = Fg + (size_t)b * LDIM_ * HW_;
    const float* p = Pg + (size_t)b * MCL_  * HW_;

    __shared__ __align__(16) float sbuf[32 * 129 + 32 * 65];
    float (*Fs)[129] = (float(*)[129])sbuf;
    float (*Ps)[65]  = (float(*)[65])(sbuf + 32 * 129);

    const int tid = threadIdx.x;
    const int tr = tid >> 4, tc = tid & 15;

    float acc[8][4];
    #pragma unroll
    for (int i = 0; i < 8; i++)
        #pragma unroll
        for (int j = 0; j < 4; j++) acc[i][j] = 0.f;

    const int nbeg = sl * 256, nend = nbeg + 256;
    for (int n0 = nbeg; n0 < nend; n0 += 32) {
        #pragma unroll
        for (int q = 0; q < 16; q++) {
            int idx = tid + q * 256;
            int l = idx >> 5, n = idx & 31;
            Fs[n][l] = f[(size_t)l * HW_ + n0 + n];
        }
        #pragma unroll
        for (int q = 0; q < 8; q++) {
            int idx = tid + q * 256;
            int m = idx >> 5, n = idx & 31;
            Ps[n][m] = p[(size_t)m * HW_ + n0 + n];
        }
        __syncthreads();

        #pragma unroll
        for (int n = 0; n < 32; n++) {
            float rf[8], rp[4];
            #pragma unroll
            for (int i = 0; i < 8; i++) rf[i] = Fs[n][tr*8 + i];
            #pragma unroll
            for (int j = 0; j < 4; j++) rp[j] = Ps[n][tc*4 + j];
            #pragma unroll
            for (int i = 0; i < 8; i++)
                #pragma unroll
                for (int j = 0; j < 4; j++)
                    acc[i][j] = fmaf(rf[i], rp[j], acc[i][j]);
        }
        __syncthreads();
    }

    float* dst = g_aggp + (((size_t)sl * B_ + b) * LDIM_) * MCL_;
    #pragma unroll
    for (int i = 0; i < 8; i++)
        #pragma unroll
        for (int j = 0; j < 4; j++)
            dst[(size_t)(tr*8 + i) * MCL_ + tc*4 + j] = acc[i][j];
}

// -------------------------------------------------------------------------
// agg_final: sum 4 partials, per-cluster L2, THEN full-row L2 (fused).
// -------------------------------------------------------------------------
__global__ void __launch_bounds__(256)
agg_final(float* __restrict__ out)
{
    const int b = blockIdx.x;
    __shared__ __align__(16) float sbuf[128 * 65 + 64 + 8];
    float (*Cs)[65] = (float(*)[65])sbuf;
    float* nrm = sbuf + 128 * 65;
    float* red = nrm + 64;
    const int tid = threadIdx.x, warp = tid >> 5, lane = tid & 31;
    float* row = out + (size_t)b * OUTD_;

    #pragma unroll
    for (int q = 0; q < 32; q++) {
        int idx = tid + q * 256;
        int l = idx >> 6, m = idx & 63;
        float s = 0.f;
        #pragma unroll
        for (int sl = 0; sl < 4; sl++)
            s += g_aggp[(((size_t)sl * B_ + b) * LDIM_ + l) * MCL_ + m];
        Cs[l][m] = s;
    }
    __syncthreads();
    if (tid < MCL_) {
        float s = 0.f;
        for (int l = 0; l < LDIM_; l++) { float c = Cs[l][tid]; s += c * c; }
        nrm[tid] = 1.f / fmaxf(sqrtf(s), EPSV);
    }
    __syncthreads();

    const float vtok = row[tid];
    float sq = vtok * vtok;
    #pragma unroll
    for (int q = 0; q < 32; q++) {
        int idx = tid + q * 256;
        int l = idx >> 6, m = idx & 63;
        float val = Cs[l][m] * nrm[m];
        sq += val * val;
    }
    #pragma unroll
    for (int o = 16; o; o >>= 1) sq += __shfl_xor_sync(0xffffffffu, sq, o);
    if (lane == 0) red[warp] = sq;
    __syncthreads();
    if (warp == 0) {
        float r = (lane < 8) ? red[lane] : 0.f;
        #pragma unroll
        for (int o = 4; o; o >>= 1) r += __shfl_xor_sync(0xffffffffu, r, o);
        if (lane == 0) red[0] = r;
    }
    __syncthreads();
    const float inv = 1.f / fmaxf(sqrtf(red[0]), EPSV);

    row[tid] = vtok * inv;
    #pragma unroll
    for (int q = 0; q < 32; q++) {
        int idx = tid + q * 256;
        int l = idx >> 6, m = idx & 63;
        row[GDIM_ + idx] = Cs[l][m] * nrm[m] * inv;
    }
}

// -------------------------------------------------------------------------
// Launch
// -------------------------------------------------------------------------
extern "C" void kernel_launch(void* const* d_in, const int* in_sizes, int n_in,
                              void* d_out, int out_size)
{
    const float* x     = (const float*)d_in[0];
    const float* t     = (const float*)d_in[1];
    const float* cf_w1 = (const float*)d_in[2];
    const float* cf_b1 = (const float*)d_in[3];
    const float* cf_w2 = (const float*)d_in[4];
    const float* cf_b2 = (const float*)d_in[5];
    const float* sc_w1 = (const float*)d_in[6];
    const float* sc_b1 = (const float*)d_in[7];
    const float* sc_w2 = (const float*)d_in[8];
    const float* sc_b2 = (const float*)d_in[9];
    const float* tk_w1 = (const float*)d_in[10];
    const float* tk_b1 = (const float*)d_in[11];
    const float* tk_w2 = (const float*)d_in[12];
    const float* tk_b2 = (const float*)d_in[13];
    const float* dust  = (const float*)d_in[14];
    float* out = (float*)d_out;

    __half *x16, *W1, *W2, *Ht;
    float *b1s, *b2s, *F, *P;
    cudaGetSymbolAddress((void**)&x16, g_x16);
    cudaGetSymbolAddress((void**)&W1,  g_W1);
    cudaGetSymbolAddress((void**)&W2,  g_W2);
    cudaGetSymbolAddress((void**)&Ht,  g_Ht);
    cudaGetSymbolAddress((void**)&b1s, g_b1s);
    cudaGetSymbolAddress((void**)&b2s, g_b2s);
    cudaGetSymbolAddress((void**)&F,   g_F);
    cudaGetSymbolAddress((void**)&P,   g_P);

    cudaFuncSetAttribute((gemm_mma<1536, 1536, 1, 128, 0>),
                         cudaFuncAttributeMaxDynamicSharedMemorySize, SMEM_G(128));
    cudaFuncSetAttribute((gemm_mma<512, 1024, 2, 128, 0>),
                         cudaFuncAttributeMaxDynamicSharedMemorySize, SMEM_G(128));
    cudaFuncSetAttribute((gemm_mma<512, 1024, 2, 64, 512>),
                         cudaFuncAttributeMaxDynamicSharedMemorySize, SMEM_G(64));
    cudaFuncSetAttribute(sinkhorn_cluster,
                         cudaFuncAttributeMaxDynamicSharedMemorySize, SK_SMEM);

    // Prep: weights fp16 + token MLP + x fp16 convert (one launch)
    prep_all<<<2080, 256>>>(cf_w1, cf_b1, sc_w1, sc_b1,
                            cf_w2, cf_b2, sc_w2, sc_b2,
                            x, t, tk_w1, tk_b1, tk_w2, tk_b2, out);

    // Layer 1 (fused cf+sc): Ht = relu(W1 @ x + b1), fp16 CHANNEL-major
    gemm_mma<1536, 1536, 1, 128, 0><<<dim3(HW_/128, 8, B_), 256, SMEM_G(128)>>>(
        W1, x16, b1s, Ht, nullptr);

    // Layer 2, exact-size: F (M=128, ch 0..511) and P (M=64, ch 512..1023)
    gemm_mma<512, 1024, 2, 128, 0><<<dim3(HW_/128, 1, B_), 256, SMEM_G(128)>>>(
        W2, Ht, b2s, nullptr, F);
    gemm_mma<512, 1024, 2, 64, 512><<<dim3(HW_/128, 1, B_), 256, SMEM_G(64)>>>(
        W2 + (size_t)LDIM_ * HID_, Ht, b2s + LDIM_, nullptr, P);

    // Cluster Sinkhorn + VLAD agg + fused final norms
    sinkhorn_cluster<<<2 * B_, 1024, SK_SMEM>>>(P, dust);
    agg_partial<<<dim3(4, B_), 256>>>(F, P);
    agg_final<<<B_, 256>>>(out);
}

// round 16
// speedup vs baseline: 1.4025x; 1.4025x over previous
#include <cuda_runtime.h>
#include <cuda_fp16.h>
#include <cooperative_groups.h>
#include <math.h>
#include <stdint.h>

namespace cg = cooperative_groups;

// Problem constants
#define B_    32
#define C_    1536
#define HW_   1024      // 32*32
#define HID_  512
#define LDIM_ 128
#define MCL_  64
#define GDIM_ 256
#define OUTD_ (GDIM_ + LDIM_*MCL_)   // 8448
#define EPSV  1e-12f

// -------------------------------------------------------------------------
// Scratch (__device__ globals: allocation-free, graph-capture safe)
// -------------------------------------------------------------------------
__device__ __align__(256) __half g_xT[(size_t)B_ * HW_ * C_];     // pixel-major fp16
__device__ __align__(256) __half g_W1[1024 * C_];
__device__ __align__(256) __half g_W2[256 * HID_];                // 0..127 cf, 128..191 sc
__device__ __align__(256) float  g_b1s[1024];
__device__ __align__(256) float  g_b2s[256];
__device__ __align__(256) __half g_Ht[(size_t)B_ * HW_ * 1024];   // pixel-major fp16
__device__ __align__(256) float  g_F[(size_t)B_ * LDIM_ * HW_];
__device__ __align__(256) float  g_P[(size_t)B_ * MCL_  * HW_];
__device__ __align__(256) float  g_aggp[4 * B_ * LDIM_ * MCL_];   // 4 HW-slices

// -------------------------------------------------------------------------
// PTX helpers
// -------------------------------------------------------------------------
__device__ __forceinline__ uint32_t smem_u32(const void* p) {
    uint32_t a;
    asm("{ .reg .u64 t; cvta.to.shared.u64 t, %1; cvt.u32.u64 %0, t; }" : "=r"(a) : "l"(p));
    return a;
}
__device__ __forceinline__ void cp16(uint32_t dst, const void* src) {
    asm volatile("cp.async.cg.shared.global [%0], [%1], 16;" :: "r"(dst), "l"(src));
}
#define CP_COMMIT() asm volatile("cp.async.commit_group;" ::: "memory")
#define CP_WAIT(n)  asm volatile("cp.async.wait_group %0;" :: "n"(n) : "memory")

__device__ __forceinline__ void ldsm4(uint32_t* r, uint32_t addr) {
    asm volatile("ldmatrix.sync.aligned.m8n8.x4.shared.b16 {%0,%1,%2,%3}, [%4];"
        : "=r"(r[0]), "=r"(r[1]), "=r"(r[2]), "=r"(r[3]) : "r"(addr));
}
__device__ __forceinline__ void mma16816(float* c, const uint32_t* a, const uint32_t* b) {
    asm volatile(
        "mma.sync.aligned.m16n8k16.row.col.f32.f16.f16.f32 "
        "{%0,%1,%2,%3}, {%4,%5,%6,%7}, {%8,%9}, {%0,%1,%2,%3};"
        : "+f"(c[0]), "+f"(c[1]), "+f"(c[2]), "+f"(c[3])
        : "r"(a[0]), "r"(a[1]), "r"(a[2]), "r"(a[3]), "r"(b[0]), "r"(b[1]));
}
__device__ __forceinline__ uint32_t swz(uint32_t off) {
    return off ^ ((off >> 3) & 0x70);
}

// -------------------------------------------------------------------------
// prep_all: weight stacking/fp16 + token MLP + x transpose/fp16, one launch.
// blocks [0,1024): W1 rows; [1024,1280): W2 rows; [1280,1312): token batches;
// [1312,13600): x transpose tiles (64ch x 64px), tile id = bx-1312 decomposed
// as (n-tile 16, c-tile 24, batch 32).
// -------------------------------------------------------------------------
__global__ void __launch_bounds__(256)
prep_all(const float* __restrict__ cf_w1, const float* __restrict__ cf_b1,
         const float* __restrict__ sc_w1, const float* __restrict__ sc_b1,
         const float* __restrict__ cf_w2, const float* __restrict__ cf_b2,
         const float* __restrict__ sc_w2, const float* __restrict__ sc_b2,
         const float* __restrict__ x,
         const float* __restrict__ t,
         const float* __restrict__ tw1, const float* __restrict__ tb1,
         const float* __restrict__ tw2, const float* __restrict__ tb2,
         float* __restrict__ out)
{
    const int bx = blockIdx.x;
    const int tid = threadIdx.x;

    if (bx < 1024) {                          // --- W1 row ---
        const int r = bx;
        const float* src = (r < HID_) ? cf_w1 + (size_t)r * C_ : sc_w1 + (size_t)(r - HID_) * C_;
        for (int i = tid; i < C_; i += 256)
            g_W1[(size_t)r * C_ + i] = __float2half_rn(src[i]);
        if (tid == 0)
            g_b1s[r] = (r < HID_) ? cf_b1[r] : sc_b1[r - HID_];
        return;
    }
    if (bx < 1280) {                          // --- W2 row ---
        const int r = bx - 1024;
        const float* src = (r < LDIM_) ? cf_w2 + (size_t)r * HID_
                         : (r < LDIM_ + MCL_) ? sc_w2 + (size_t)(r - LDIM_) * HID_ : nullptr;
        for (int i = tid; i < HID_; i += 256)
            g_W2[(size_t)r * HID_ + i] = __float2half_rn(src ? src[i] : 0.f);
        if (tid == 0)
            g_b2s[r] = (r < LDIM_) ? cf_b2[r] : (r < LDIM_ + MCL_) ? sc_b2[r - LDIM_] : 0.f;
        return;
    }
    if (bx >= 1312) {                         // --- x transpose tile ---
        __shared__ float s[64][65];
        const int tile = bx - 1312;           // 0..12287
        const int nt = tile & 15;             // 16 n-tiles
        const int ct = (tile >> 4) % 24;      // 24 c-tiles
        const int b  = tile / (16 * 24);      // 32 batches
        const int n0 = nt * 64, c0 = ct * 64;

        #pragma unroll
        for (int q = 0; q < 4; q++) {
            int idx = tid + q * 256;          // 1024 float4s = 64 rows x 16
            int row = idx >> 4, p4 = (idx & 15) * 4;
            float4 v = *(const float4*)(x + ((size_t)b * C_ + c0 + row) * HW_ + n0 + p4);
            s[row][p4 + 0] = v.x; s[row][p4 + 1] = v.y;
            s[row][p4 + 2] = v.z; s[row][p4 + 3] = v.w;
        }
        __syncthreads();

        #pragma unroll
        for (int q = 0; q < 2; q++) {
            int idx = tid + q * 256;          // 512 = 64px x 8 ch-groups
            int px = idx >> 3, cgr = (idx & 7) * 8;
            __half h8[8];
            #pragma unroll
            for (int j = 0; j < 8; j++) h8[j] = __float2half_rn(s[cgr + j][px]);
            size_t g = ((size_t)b * HW_ + n0 + px) * C_ + c0 + cgr;
            *(uint4*)(g_xT + g) = *(const uint4*)h8;
        }
        return;
    }

    // --- token MLP for batch b ---
    const int b = bx - 1280;
    const int warp = tid >> 5, lane = tid & 31;

    __shared__ float ts[C_];
    __shared__ float h[HID_];
    __shared__ float tk[GDIM_];
    __shared__ float red[8];

    for (int i = tid; i < C_; i += 256) ts[i] = t[(size_t)b * C_ + i];
    __syncthreads();

    for (int j = warp; j < HID_; j += 8) {
        const float* wr = tw1 + (size_t)j * C_;
        float s = 0.f;
        for (int k = lane * 4; k < C_; k += 128) {
            float4 w4 = *(const float4*)(wr + k);
            float4 t4 = *(const float4*)(ts + k);
            s += w4.x*t4.x + w4.y*t4.y + w4.z*t4.z + w4.w*t4.w;
        }
        #pragma unroll
        for (int o = 16; o; o >>= 1) s += __shfl_xor_sync(0xffffffffu, s, o);
        if (lane == 0) h[j] = fmaxf(s + tb1[j], 0.f);
    }
    __syncthreads();

    for (int j = warp; j < GDIM_; j += 8) {
        const float* wr = tw2 + (size_t)j * HID_;
        float s = 0.f;
        for (int k = lane * 4; k < HID_; k += 128) {
            float4 w4 = *(const float4*)(wr + k);
            float4 h4 = *(const float4*)(h + k);
            s += w4.x*h4.x + w4.y*h4.y + w4.z*h4.z + w4.w*h4.w;
        }
        #pragma unroll
        for (int o = 16; o; o >>= 1) s += __shfl_xor_sync(0xffffffffu, s, o);
        if (lane == 0) tk[j] = s + tb2[j];
    }
    __syncthreads();

    float v = tk[tid];
    float sq = v * v;
    #pragma unroll
    for (int o = 16; o; o >>= 1) sq += __shfl_xor_sync(0xffffffffu, sq, o);
    if (lane == 0) red[warp] = sq;
    __syncthreads();
    if (warp == 0) {
        float r = (lane < 8) ? red[lane] : 0.f;
        #pragma unroll
        for (int o = 4; o; o >>= 1) r += __shfl_xor_sync(0xffffffffu, r, o);
        if (lane == 0) red[0] = r;
    }
    __syncthreads();
    const float inv = 1.f / fmaxf(sqrtf(red[0]), EPSV);
    out[(size_t)b * OUTD_ + tid] = v * inv;
}

// -------------------------------------------------------------------------
// Tensor-core GEMM via mma.sync (single-pass fp16, fp32 accum). R14 winner.
// CTA = CTAM x 128 (CTAM in {128,64}), 8 warps @ (CTAM/2)x32, BK=64,
// 3-stage cp.async pipeline, __launch_bounds__(256,2).
// EPI=1: bias+relu -> fp16 -> pixel-major Ht (CTAM=128 only).
// EPI=2: bias -> fp32, contiguous M rows to Out (F or P), channel-major.
// KOFF: column offset into the B operand rows (Ht channel half).
// -------------------------------------------------------------------------
template<int KDIM, int BSTR, int EPI, int CTAM, int KOFF>
__global__ void __launch_bounds__(256, 2)
gemm_mma(const __half* __restrict__ Ag, const __half* __restrict__ Bg,
         const float* __restrict__ bias,
         __half* __restrict__ OutH, float* __restrict__ OutF)
{
    constexpr int NCHUNK  = KDIM / 64;
    constexpr int A_BYTES = CTAM * 128;
    constexpr int STAGE   = A_BYTES + 16384;
    constexpr int MB = CTAM / 32, NB = 4, NBP = 2;  // warp tile (CTAM/2) x 32
    constexpr int AIT = (CTAM * 8) / 256;

    extern __shared__ __align__(1024) char smem[];
    const uint32_t sbase = smem_u32(smem);
    float* bias_s = (float*)smem;

    const int tid  = threadIdx.x;
    const int wid  = tid >> 5, lane = tid & 31;
    const int n0   = blockIdx.x * 128;
    const int m0   = blockIdx.y * CTAM;
    const int bz   = blockIdx.z;

    const int warp_m = (wid >> 2) * (CTAM / 2);
    const int warp_n = (wid & 3) * 32;

    if (tid < CTAM) bias_s[tid] = bias[m0 + tid];

    const size_t bRow = (size_t)bz * HW_ + n0;

    auto load_stage = [&](int c, int stage) {
        const uint32_t base = sbase + 1024 + stage * STAGE;
        #pragma unroll
        for (int q = 0; q < AIT; q++) {
            int idx = tid + q * 256;
            int row = idx >> 3, seg = idx & 7;
            cp16(base + swz(row * 128 + seg * 16),
                 Ag + (size_t)(m0 + row) * KDIM + c * 64 + seg * 8);
        }
        const uint32_t bbuf = base + A_BYTES;
        #pragma unroll
        for (int q = 0; q < 4; q++) {
            int idx = tid + q * 256;
            int row = idx >> 3, seg = idx & 7;
            cp16(bbuf + swz(row * 128 + seg * 16),
                 Bg + (bRow + row) * BSTR + KOFF + c * 64 + seg * 8);
        }
        CP_COMMIT();
    };

    float acc[MB][NB][4];
    #pragma unroll
    for (int i = 0; i < MB; i++)
        #pragma unroll
        for (int j = 0; j < NB; j++)
            #pragma unroll
            for (int r = 0; r < 4; r++) acc[i][j][r] = 0.f;

    load_stage(0, 0);
    if (NCHUNK > 1) load_stage(1, 1);

    #pragma unroll 1
    for (int c = 0; c < NCHUNK; c++) {
        if (c + 1 < NCHUNK) { CP_WAIT(1); }
        else                { CP_WAIT(0); }
        __syncthreads();

        if (c + 2 < NCHUNK) load_stage(c + 2, (c + 2) % 3);

        const uint32_t aBase = sbase + 1024 + (c % 3) * STAGE;
        const uint32_t bBase = aBase + A_BYTES;

        #pragma unroll
        for (int s = 0; s < 4; s++) {
            uint32_t af[MB][4], bf[NB][2];
            #pragma unroll
            for (int mb = 0; mb < MB; mb++) {
                int row = warp_m + mb * 16 + (lane & 15);
                uint32_t off = swz(row * 128 + s * 32 + ((lane >> 4) << 4));
                ldsm4(af[mb], aBase + off);
            }
            #pragma unroll
            for (int nbp = 0; nbp < NBP; nbp++) {
                int grp = lane >> 3;
                int row = warp_n + nbp * 16 + ((grp >> 1) << 3) + (lane & 7);
                uint32_t off = swz(row * 128 + s * 32 + ((grp & 1) << 4));
                uint32_t t[4];
                ldsm4(t, bBase + off);
                bf[nbp*2][0] = t[0]; bf[nbp*2][1] = t[1];
                bf[nbp*2+1][0] = t[2]; bf[nbp*2+1][1] = t[3];
            }
            #pragma unroll
            for (int mb = 0; mb < MB; mb++)
                #pragma unroll
                for (int nb = 0; nb < NB; nb++) mma16816(acc[mb][nb], af[mb], bf[nb]);
        }
    }
    __syncthreads();

    const int qr = lane >> 2, qc = (lane & 3) * 2;

    if (EPI == 1) {
        constexpr int PITCH = CTAM + 4;
        float* sC = (float*)(smem + 1024);
        #pragma unroll
        for (int mb = 0; mb < MB; mb++)
            #pragma unroll
            for (int nb = 0; nb < NB; nb++)
                #pragma unroll
                for (int r = 0; r < 4; r++) {
                    int m = warp_m + mb * 16 + qr + ((r >> 1) << 3);
                    int n = warp_n + nb * 8 + qc + (r & 1);
                    sC[n * PITCH + m] = fmaxf(acc[mb][nb][r] + bias_s[m], 0.f);
                }
        __syncthreads();
        constexpr int SEGS = CTAM / 8;
        #pragma unroll
        for (int q = 0; q < (128 * SEGS) / 256; q++) {
            int idx = tid + q * 256;
            int px = idx / SEGS, sg = idx % SEGS;
            const float* src = sC + px * PITCH + sg * 8;
            __half h8[8];
            #pragma unroll
            for (int j = 0; j < 8; j++) h8[j] = __float2half_rn(src[j]);
            size_t g = ((size_t)bz * HW_ + n0 + px) * 1024 + m0 + sg * 8;
            *(uint4*)(OutH + g) = *(const uint4*)h8;
        }
    } else {
        #pragma unroll
        for (int mb = 0; mb < MB; mb++)
            #pragma unroll
            for (int nb = 0; nb < NB; nb++)
                #pragma unroll
                for (int r = 0; r < 4; r++) {
                    int ml = warp_m + mb * 16 + qr + ((r >> 1) << 3);
                    int n  = warp_n + nb * 8 + qc + (r & 1);
                    OutF[((size_t)bz * CTAM + m0 + ml) * HW_ + n0 + n]
                        = acc[mb][nb][r] + bias_s[ml];
                }
    }
}

#define SMEM_G(CTAM) (1024 + 3 * ((CTAM) * 128 + 16384))

// -------------------------------------------------------------------------
// Cluster Sinkhorn (R11 winner, unchanged)
// -------------------------------------------------------------------------
#define SK_COLS 512
#define SK_SMEM ((64 * SK_COLS + 72 + SK_COLS + 2 * 66 + 2 * 66) * 4)

__global__ void __launch_bounds__(1024) __cluster_dims__(2, 1, 1)
sinkhorn_cluster(float* __restrict__ Pg, const float* __restrict__ dust)
{
    extern __shared__ float sk[];
    float* Zs = sk;
    float* u  = sk + 64 * SK_COLS;
    float* v  = u + 72;
    float* pm = v + SK_COLS;
    float* ps = pm + 2 * 66;

    cg::cluster_group cluster = cg::this_cluster();
    const int rank = blockIdx.x & 1;
    const int b    = blockIdx.x >> 1;
    float* Z = Pg + (size_t)b * MCL_ * HW_ + rank * SK_COLS;
    const int tid = threadIdx.x, warp = tid >> 5, lane = tid & 31;

    const float alpha = dust[0];
    const float norm_c     = -logf((float)(MCL_ + HW_));
    const float log_mu     = norm_c;
    const float log_mu_bin = logf((float)(HW_ - MCL_)) + norm_c;
    const float log_nu     = norm_c;

    for (int idx = tid; idx < 64 * SK_COLS; idx += 1024)
        Zs[idx] = Z[(size_t)(idx >> 9) * HW_ + (idx & 511)];
    if (tid < SK_COLS) v[tid] = 0.f;
    __syncthreads();

    float* peer_pm = cluster.map_shared_rank(pm, rank ^ 1);
    float* peer_ps = cluster.map_shared_rank(ps, rank ^ 1);

    for (int it = 0; it < 3; it++) {
        float* pmx = pm + (it & 1) * 66;
        float* psm = ps + (it & 1) * 66;
        float* qmx = peer_pm + (it & 1) * 66;
        float* qsm = peer_ps + (it & 1) * 66;

        for (int i = warp; i < MCL_; i += 32) {
            const float* zr = Zs + i * SK_COLS;
            float mx = -3.0e38f, s = 0.f;
            for (int j = lane; j < SK_COLS; j += 32) {
                float zv = zr[j] + v[j];
                if (zv > mx) { s = s * __expf(mx - zv) + 1.f; mx = zv; }
                else           s += __expf(zv - mx);
            }
            #pragma unroll
            for (int o = 16; o; o >>= 1) {
                float mo = __shfl_xor_sync(0xffffffffu, mx, o);
                float so = __shfl_xor_sync(0xffffffffu, s,  o);
                float m2 = fmaxf(mx, mo);
                s  = s * __expf(mx - m2) + so * __expf(mo - m2);
                mx = m2;
            }
            if (lane == 0) { pmx[i] = mx; psm[i] = s; }
        }
        if (warp == 0) {
            float mx = -3.0e38f, s = 0.f;
            for (int j = lane; j < SK_COLS; j += 32) {
                float zv = v[j];
                if (zv > mx) { s = s * __expf(mx - zv) + 1.f; mx = zv; }
                else           s += __expf(zv - mx);
            }
            #pragma unroll
            for (int o = 16; o; o >>= 1) {
                float mo = __shfl_xor_sync(0xffffffffu, mx, o);
                float so = __shfl_xor_sync(0xffffffffu, s,  o);
                float m2 = fmaxf(mx, mo);
                s  = s * __expf(mx - m2) + so * __expf(mo - m2);
                mx = m2;
            }
            if (lane == 0) { pmx[MCL_] = mx; psm[MCL_] = s; }
        }
        cluster.sync();

        if (tid <= MCL_) {
            float mA = pmx[tid], sA = psm[tid];
            float mB = qmx[tid], sB = qsm[tid];
            float M = fmaxf(mA, mB);
            float lse = M + __logf(sA * __expf(mA - M) + sB * __expf(mB - M));
            u[tid] = (tid < MCL_) ? (log_mu - lse) : (log_mu_bin - (alpha + lse));
        }
        __syncthreads();

        if (tid < SK_COLS) {
            const int j = tid;
            float mx = alpha + u[MCL_];
            float s  = 1.f;
            #pragma unroll 4
            for (int i = 0; i < MCL_; i++) {
                float zv = Zs[i * SK_COLS + j] + u[i];
                if (zv > mx) { s = s * __expf(mx - zv) + 1.f; mx = zv; }
                else           s += __expf(zv - mx);
            }
            v[j] = log_nu - (mx + __logf(s));
        }
        __syncthreads();
    }

    for (int idx = tid; idx < 64 * SK_COLS; idx += 1024) {
        int i = idx >> 9, j = idx & 511;
        Z[(size_t)i * HW_ + j] = __expf(Zs[idx] + u[i] + v[j] - norm_c);
    }
    cluster.sync();
}

// -------------------------------------------------------------------------
// VLAD aggregation, stage 1: partial agg over an HW quarter.
// -------------------------------------------------------------------------
__global__ void __launch_bounds__(256)
agg_partial(const float* __restrict__ Fg, const float* __restrict__ Pg)
{
    const int sl = blockIdx.x;
    const int b  = blockIdx.y;
    const float* f = Fg + (size_t)b * LDIM_ * HW_;
    const float* p = Pg + (size_t)b * MCL_  * HW_;

    __shared__ __align__(16) float sbuf[32 * 129 + 32 * 65];
    float (*Fs)[129] = (float(*)[129])sbuf;
    float (*Ps)[65]  = (float(*)[65])(sbuf + 32 * 129);

    const int tid = threadIdx.x;
    const int tr = tid >> 4, tc = tid & 15;

    float acc[8][4];
    #pragma unroll
    for (int i = 0; i < 8; i++)
        #pragma unroll
        for (int j = 0; j < 4; j++) acc[i][j] = 0.f;

    const int nbeg = sl * 256, nend = nbeg + 256;
    for (int n0 = nbeg; n0 < nend; n0 += 32) {
        #pragma unroll
        for (int q = 0; q < 16; q++) {
            int idx = tid + q * 256;
            int l = idx >> 5, n = idx & 31;
            Fs[n][l] = f[(size_t)l * HW_ + n0 + n];
        }
        #pragma unroll
        for (int q = 0; q < 8; q++) {
            int idx = tid + q * 256;
            int m = idx >> 5, n = idx & 31;
            Ps[n][m] = p[(size_t)m * HW_ + n0 + n];
        }
        __syncthreads();

        #pragma unroll
        for (int n = 0; n < 32; n++) {
            float rf[8], rp[4];
            #pragma unroll
            for (int i = 0; i < 8; i++) rf[i] = Fs[n][tr*8 + i];
            #pragma unroll
            for (int j = 0; j < 4; j++) rp[j] = Ps[n][tc*4 + j];
            #pragma unroll
            for (int i = 0; i < 8; i++)
                #pragma unroll
                for (int j = 0; j < 4; j++)
                    acc[i][j] = fmaf(rf[i], rp[j], acc[i][j]);
        }
        __syncthreads();
    }

    float* dst = g_aggp + (((size_t)sl * B_ + b) * LDIM_) * MCL_;
    #pragma unroll
    for (int i = 0; i < 8; i++)
        #pragma unroll
        for (int j = 0; j < 4; j++)
            dst[(size_t)(tr*8 + i) * MCL_ + tc*4 + j] = acc[i][j];
}

// -------------------------------------------------------------------------
// agg_final: sum 4 partials, per-cluster L2, THEN full-row L2 (fused).
// -------------------------------------------------------------------------
__global__ void __launch_bounds__(256)
agg_final(float* __restrict__ out)
{
    const int b = blockIdx.x;
    __shared__ __align__(16) float sbuf[128 * 65 + 64 + 8];
    float (*Cs)[65] = (float(*)[65])sbuf;
    float* nrm = sbuf + 128 * 65;
    float* red = nrm + 64;
    const int tid = threadIdx.x, warp = tid >> 5, lane = tid & 31;
    float* row = out + (size_t)b * OUTD_;

    #pragma unroll
    for (int q = 0; q < 32; q++) {
        int idx = tid + q * 256;
        int l = idx >> 6, m = idx & 63;
        float s = 0.f;
        #pragma unroll
        for (int sl = 0; sl < 4; sl++)
            s += g_aggp[(((size_t)sl * B_ + b) * LDIM_ + l) * MCL_ + m];
        Cs[l][m] = s;
    }
    __syncthreads();
    if (tid < MCL_) {
        float s = 0.f;
        for (int l = 0; l < LDIM_; l++) { float c = Cs[l][tid]; s += c * c; }
        nrm[tid] = 1.f / fmaxf(sqrtf(s), EPSV);
    }
    __syncthreads();

    const float vtok = row[tid];
    float sq = vtok * vtok;
    #pragma unroll
    for (int q = 0; q < 32; q++) {
        int idx = tid + q * 256;
        int l = idx >> 6, m = idx & 63;
        float val = Cs[l][m] * nrm[m];
        sq += val * val;
    }
    #pragma unroll
    for (int o = 16; o; o >>= 1) sq += __shfl_xor_sync(0xffffffffu, sq, o);
    if (lane == 0) red[warp] = sq;
    __syncthreads();
    if (warp == 0) {
        float r = (lane < 8) ? red[lane] : 0.f;
        #pragma unroll
        for (int o = 4; o; o >>= 1) r += __shfl_xor_sync(0xffffffffu, r, o);
        if (lane == 0) red[0] = r;
    }
    __syncthreads();
    const float inv = 1.f / fmaxf(sqrtf(red[0]), EPSV);

    row[tid] = vtok * inv;
    #pragma unroll
    for (int q = 0; q < 32; q++) {
        int idx = tid + q * 256;
        int l = idx >> 6, m = idx & 63;
        row[GDIM_ + idx] = Cs[l][m] * nrm[m] * inv;
    }
}

// -------------------------------------------------------------------------
// Launch
// -------------------------------------------------------------------------
extern "C" void kernel_launch(void* const* d_in, const int* in_sizes, int n_in,
                              void* d_out, int out_size)
{
    const float* x     = (const float*)d_in[0];
    const float* t     = (const float*)d_in[1];
    const float* cf_w1 = (const float*)d_in[2];
    const float* cf_b1 = (const float*)d_in[3];
    const float* cf_w2 = (const float*)d_in[4];
    const float* cf_b2 = (const float*)d_in[5];
    const float* sc_w1 = (const float*)d_in[6];
    const float* sc_b1 = (const float*)d_in[7];
    const float* sc_w2 = (const float*)d_in[8];
    const float* sc_b2 = (const float*)d_in[9];
    const float* tk_w1 = (const float*)d_in[10];
    const float* tk_b1 = (const float*)d_in[11];
    const float* tk_w2 = (const float*)d_in[12];
    const float* tk_b2 = (const float*)d_in[13];
    const float* dust  = (const float*)d_in[14];
    float* out = (float*)d_out;

    __half *xT, *W1, *W2, *Ht;
    float *b1s, *b2s, *F, *P;
    cudaGetSymbolAddress((void**)&xT,  g_xT);
    cudaGetSymbolAddress((void**)&W1,  g_W1);
    cudaGetSymbolAddress((void**)&W2,  g_W2);
    cudaGetSymbolAddress((void**)&Ht,  g_Ht);
    cudaGetSymbolAddress((void**)&b1s, g_b1s);
    cudaGetSymbolAddress((void**)&b2s, g_b2s);
    cudaGetSymbolAddress((void**)&F,   g_F);
    cudaGetSymbolAddress((void**)&P,   g_P);

    cudaFuncSetAttribute((gemm_mma<1536, 1536, 1, 128, 0>),
                         cudaFuncAttributeMaxDynamicSharedMemorySize, SMEM_G(128));
    cudaFuncSetAttribute((gemm_mma<512, 1024, 2, 128, 0>),
                         cudaFuncAttributeMaxDynamicSharedMemorySize, SMEM_G(128));
    cudaFuncSetAttribute((gemm_mma<512, 1024, 2, 64, 512>),
                         cudaFuncAttributeMaxDynamicSharedMemorySize, SMEM_G(64));
    cudaFuncSetAttribute(sinkhorn_cluster,
                         cudaFuncAttributeMaxDynamicSharedMemorySize, SK_SMEM);

    // Prep: weights fp16 + token MLP + x transpose/fp16 (single launch)
    prep_all<<<13600, 256>>>(cf_w1, cf_b1, sc_w1, sc_b1,
                             cf_w2, cf_b2, sc_w2, sc_b2,
                             x, t, tk_w1, tk_b1, tk_w2, tk_b2, out);

    // Layer 1 (fused cf+sc): Ht = relu(W1 @ x + b1), fp16 pixel-major
    gemm_mma<1536, 1536, 1, 128, 0><<<dim3(HW_/128, 8, B_), 256, SMEM_G(128)>>>(
        W1, xT, b1s, Ht, nullptr);

    // Layer 2, exact-size: F (M=128, cf half) and P (M=64, sc half)
    gemm_mma<512, 1024, 2, 128, 0><<<dim3(HW_/128, 1, B_), 256, SMEM_G(128)>>>(
        W2, Ht, b2s, nullptr, F);
    gemm_mma<512, 1024, 2, 64, 512><<<dim3(HW_/128, 1, B_), 256, SMEM_G(64)>>>(
        W2 + (size_t)LDIM_ * HID_, Ht, b2s + LDIM_, nullptr, P);

    // Cluster Sinkhorn + VLAD agg + fused final norms
    sinkhorn_cluster<<<2 * B_, 1024, SK_SMEM>>>(P, dust);
    agg_partial<<<dim3(4, B_), 256>>>(F, P);
    agg_final<<<B_, 256>>>(out);
}